// round 6
// baseline (speedup 1.0000x reference)
#include <cuda_runtime.h>
#include <cuda_bf16.h>
#include <cstdint>

#define N_PTS 384
#define DIM 128
#define MARGIN 0.3f
#define GRID_B 144          // 12x12 gram tiles, < 148 SMs -> one wave
#define BLK 256
#define NWARP 8

// Scratch (no allocations allowed).
__device__ float g_gram[N_PTS * N_PTS];
__device__ float g_nrm[N_PTS];

// Generation-counter sync state: monotonically increasing across graph
// replays, so no reset is ever needed for the barrier. g_acc is reset by the
// last-ticket block each run.
__device__ unsigned int g_bar;     // grid barrier counter
__device__ unsigned int g_ticket;  // writeout ticket
__device__ float g_acc[2];

__global__ __launch_bounds__(BLK) void fused_kernel(
    const float* __restrict__ E,
    const int* __restrict__ labels,
    float* __restrict__ out, int out_size) {

    const int blk = blockIdx.x;
    const int t = threadIdx.x;
    const int lane = t & 31;
    const int warp = t >> 5;

    __shared__ float As[32][132];
    __shared__ float Bs[32][132];
    __shared__ float spos[N_PTS];
    __shared__ float sneg[N_PTS];
    __shared__ int slab[N_PTS];
    __shared__ int cnts[2];
    __shared__ float wl[NWARP], wc[NWARP];

    float* G = g_gram;
    float* nrm = g_nrm;

    // =====================================================================
    // Phase A: Gram tile (32x32), block (by, bx) of the 12x12 grid.
    // =====================================================================
    const int by = blk / 12;
    const int bx = blk % 12;
    const int bi = by * 32;
    const int bj = bx * 32;

    {
        const float4* E4 = reinterpret_cast<const float4*>(E);
        for (int v = t; v < 1024; v += BLK) {
            int r = v >> 5;
            int c4 = v & 31;
            float4 a = E4[(bi + r) * 32 + c4];
            float4 b = E4[(bj + r) * 32 + c4];
            *reinterpret_cast<float4*>(&As[r][c4 * 4]) = a;
            *reinterpret_cast<float4*>(&Bs[r][c4 * 4]) = b;
        }
        __syncthreads();

        const int ti = t >> 4;
        const int tj = t & 15;

        float acc00 = 0.f, acc01 = 0.f, acc10 = 0.f, acc11 = 0.f;

#pragma unroll 8
        for (int k4 = 0; k4 < 32; k4++) {
            float4 a0 = *reinterpret_cast<const float4*>(&As[ti][k4 * 4]);
            float4 a1 = *reinterpret_cast<const float4*>(&As[ti + 16][k4 * 4]);
            float4 b0 = *reinterpret_cast<const float4*>(&Bs[tj][k4 * 4]);
            float4 b1 = *reinterpret_cast<const float4*>(&Bs[tj + 16][k4 * 4]);
            acc00 = fmaf(a0.x, b0.x, acc00);
            acc00 = fmaf(a0.y, b0.y, acc00);
            acc00 = fmaf(a0.z, b0.z, acc00);
            acc00 = fmaf(a0.w, b0.w, acc00);
            acc01 = fmaf(a0.x, b1.x, acc01);
            acc01 = fmaf(a0.y, b1.y, acc01);
            acc01 = fmaf(a0.z, b1.z, acc01);
            acc01 = fmaf(a0.w, b1.w, acc01);
            acc10 = fmaf(a1.x, b0.x, acc10);
            acc10 = fmaf(a1.y, b0.y, acc10);
            acc10 = fmaf(a1.z, b0.z, acc10);
            acc10 = fmaf(a1.w, b0.w, acc10);
            acc11 = fmaf(a1.x, b1.x, acc11);
            acc11 = fmaf(a1.y, b1.y, acc11);
            acc11 = fmaf(a1.z, b1.z, acc11);
            acc11 = fmaf(a1.w, b1.w, acc11);
        }

        const int gi0 = bi + ti, gi1 = bi + ti + 16;
        const int gj0 = bj + tj, gj1 = bj + tj + 16;
        G[gi0 * N_PTS + gj0] = acc00;
        G[gi0 * N_PTS + gj1] = acc01;
        G[gi1 * N_PTS + gj0] = acc10;
        G[gi1 * N_PTS + gj1] = acc11;

        if (bx == by && ti == tj) {
            nrm[gi0] = acc00;
            nrm[gi1] = acc11;
        }
    }

    // Load labels into smem (overlaps with other blocks' gram work).
    for (int v = t; v < N_PTS; v += BLK) slab[v] = labels[v];

    // =====================================================================
    // Grid barrier (generation counter; one wave -> no deadlock).
    // =====================================================================
    __threadfence();   // publish G / nrm (release)
    __syncthreads();   // all threads of this block have stored + fenced
    if (t == 0) {
        unsigned int gen = atomicAdd(&g_bar, 1u) / GRID_B;
        unsigned int target = (gen + 1u) * GRID_B;
        while (*((volatile unsigned int*)&g_bar) < target) { }
    }
    __syncthreads();
    __threadfence();   // acquire

    // =====================================================================
    // Phase B: anchors a = blk, blk+144, blk+288.
    // =====================================================================
    float loss = 0.f, cnt = 0.f;

    for (int a = blk; a < N_PTS; a += GRID_B) {
        if (t < 2) cnts[t] = 0;
        __syncthreads();

        const int la = slab[a];
        const float na = nrm[a] + MARGIN;   // fold margin into the positive term

        // Compaction over two chunks of 256 (N_PTS = 384).
        for (int base = 0; base < N_PTS; base += BLK) {
            const int j = base + t;
            const bool valid = (j < N_PTS);
            float dj = 0.f;
            bool same = false;
            if (valid) {
                dj = na + nrm[j] - 2.f * G[a * N_PTS + j];  // = dist + MARGIN
                same = (slab[j] == la);
            }
            unsigned ms = __ballot_sync(0xFFFFFFFFu, valid && same);
            unsigned md = __ballot_sync(0xFFFFFFFFu, valid && !same);
            unsigned lt = (1u << lane) - 1u;

            int bp = 0, bn = 0;
            if (lane == 0) {
                bp = atomicAdd(&cnts[0], __popc(ms));
                bn = atomicAdd(&cnts[1], __popc(md));
            }
            bp = __shfl_sync(0xFFFFFFFFu, bp, 0);
            bn = __shfl_sync(0xFFFFFFFFu, bn, 0);

            if (valid) {
                if (same) spos[bp + __popc(ms & lt)] = dj;
                else      sneg[bn + __popc(md & lt)] = dj;
            }
        }
        __syncthreads();

        const int P = cnts[0];
        const int M = cnts[1];

        // spos holds dist_pos + MARGIN; sneg holds dist_neg + MARGIN.
        // L = dist_pos - dist_neg + MARGIN = spos[p] - (sneg[n] - MARGIN).
        for (int n = t; n < M; n += BLK) {
            const float dn = sneg[n] - MARGIN;
            for (int p = 0; p < P; p++) {
                float L = spos[p] - dn;
                if (L > 0.f && L < MARGIN) { loss += L; cnt += 1.f; }
            }
        }
        __syncthreads();   // protect spos/sneg/cnts reuse next anchor
    }

    // =====================================================================
    // Block reduction + global accumulate + last-block writeout.
    // =====================================================================
#pragma unroll
    for (int off = 16; off > 0; off >>= 1) {
        loss += __shfl_down_sync(0xFFFFFFFFu, loss, off);
        cnt  += __shfl_down_sync(0xFFFFFFFFu, cnt,  off);
    }
    if (lane == 0) { wl[warp] = loss; wc[warp] = cnt; }
    __syncthreads();

    if (t == 0) {
        float l = 0.f, c = 0.f;
#pragma unroll
        for (int w = 0; w < NWARP; w++) { l += wl[w]; c += wc[w]; }
        atomicAdd(&g_acc[0], l);
        atomicAdd(&g_acc[1], c);
        __threadfence();
        unsigned int done = atomicAdd(&g_ticket, 1u);
        if ((done % GRID_B) == GRID_B - 1) {
            __threadfence();
            out[0] = g_acc[0];
            out[1] = g_acc[1];
            for (int k = 2; k < out_size; k++) out[k] = 0.f;
            g_acc[0] = 0.f;
            g_acc[1] = 0.f;
        }
    }
}

extern "C" void kernel_launch(void* const* d_in, const int* in_sizes, int n_in,
                              void* d_out, int out_size) {
    const float* embeddings = (const float*)d_in[0];
    const int* labels = (const int*)d_in[1];
    float* out = (float*)d_out;

    fused_kernel<<<GRID_B, BLK>>>(embeddings, labels, out, out_size);
}

// round 9
// speedup vs baseline: 1.1800x; 1.1800x over previous
#include <cuda_runtime.h>
#include <cuda_bf16.h>
#include <cstdint>

#define N_PTS 384
#define DIM 128
#define MARGIN 0.3f
#define K2_GRID 128
#define K2_BLK 384
#define ANCH 3

// Scratch (no allocations allowed).
__device__ float g_gram[N_PTS * N_PTS];
__device__ float g_nrm[N_PTS];

// Accumulators: reset by the last-ticket block each run (graph-replay safe).
__device__ float g_acc[2];
__device__ unsigned int g_ticket;

// ---------------------------------------------------------------------------
// K1: Gram matrix G[i][j] = dot(E_i, E_j), 32x32 tiles, 2x2 register tile.
// Signals dependent launch (PDL) after its stores.
// ---------------------------------------------------------------------------
__global__ __launch_bounds__(256) void gram_kernel(const float* __restrict__ E,
                                                   float* __restrict__ G,
                                                   float* __restrict__ nrm) {
    __shared__ float As[32][132];
    __shared__ float Bs[32][132];

    const int bi = blockIdx.y * 32;
    const int bj = blockIdx.x * 32;
    const int t = threadIdx.x;

    const float4* E4 = reinterpret_cast<const float4*>(E);
    for (int v = t; v < 1024; v += 256) {
        int r = v >> 5;
        int c4 = v & 31;
        float4 a = E4[(bi + r) * 32 + c4];
        float4 b = E4[(bj + r) * 32 + c4];
        *reinterpret_cast<float4*>(&As[r][c4 * 4]) = a;
        *reinterpret_cast<float4*>(&Bs[r][c4 * 4]) = b;
    }
    __syncthreads();

    const int ti = t >> 4;
    const int tj = t & 15;

    float acc00 = 0.f, acc01 = 0.f, acc10 = 0.f, acc11 = 0.f;

#pragma unroll 8
    for (int k4 = 0; k4 < 32; k4++) {
        float4 a0 = *reinterpret_cast<const float4*>(&As[ti][k4 * 4]);
        float4 a1 = *reinterpret_cast<const float4*>(&As[ti + 16][k4 * 4]);
        float4 b0 = *reinterpret_cast<const float4*>(&Bs[tj][k4 * 4]);
        float4 b1 = *reinterpret_cast<const float4*>(&Bs[tj + 16][k4 * 4]);
        acc00 = fmaf(a0.x, b0.x, acc00);
        acc00 = fmaf(a0.y, b0.y, acc00);
        acc00 = fmaf(a0.z, b0.z, acc00);
        acc00 = fmaf(a0.w, b0.w, acc00);
        acc01 = fmaf(a0.x, b1.x, acc01);
        acc01 = fmaf(a0.y, b1.y, acc01);
        acc01 = fmaf(a0.z, b1.z, acc01);
        acc01 = fmaf(a0.w, b1.w, acc01);
        acc10 = fmaf(a1.x, b0.x, acc10);
        acc10 = fmaf(a1.y, b0.y, acc10);
        acc10 = fmaf(a1.z, b0.z, acc10);
        acc10 = fmaf(a1.w, b0.w, acc10);
        acc11 = fmaf(a1.x, b1.x, acc11);
        acc11 = fmaf(a1.y, b1.y, acc11);
        acc11 = fmaf(a1.z, b1.z, acc11);
        acc11 = fmaf(a1.w, b1.w, acc11);
    }

    const int gi0 = bi + ti, gi1 = bi + ti + 16;
    const int gj0 = bj + tj, gj1 = bj + tj + 16;
    G[gi0 * N_PTS + gj0] = acc00;
    G[gi0 * N_PTS + gj1] = acc01;
    G[gi1 * N_PTS + gj0] = acc10;
    G[gi1 * N_PTS + gj1] = acc11;

    if (blockIdx.x == blockIdx.y && ti == tj) {
        nrm[gi0] = acc00;
        nrm[gi1] = acc11;
    }

    // PDL: allow the dependent kernel's blocks to launch now.
    __threadfence();
    asm volatile("griddepcontrol.launch_dependents;");
}

// ---------------------------------------------------------------------------
// K2: 128 blocks x 384 threads, 3 anchors per block.
// Prologue runs before griddepcontrol.wait (overlapped with K1 via PDL).
// Batched G-row loads, ballot compaction, thread-holds-negative pair loop.
// ---------------------------------------------------------------------------
__global__ __launch_bounds__(K2_BLK) void triplet_kernel(
    const float* __restrict__ G,
    const float* __restrict__ nrm,
    const int* __restrict__ labels,
    float* __restrict__ out, int out_size) {

    const int blk = blockIdx.x;
    const int t = threadIdx.x;
    const int lane = t & 31;
    const int warp = t >> 5;       // 12 warps
    const int a0 = blk * ANCH;

    __shared__ float spos[ANCH][N_PTS];
    __shared__ float sneg[ANCH][N_PTS];
    __shared__ int cnts[ANCH][2];
    __shared__ float wl[12], wc[12];

    // ---- Prologue (runs before K1 finishes) ----
    if (t < ANCH * 2) ((int*)cnts)[t] = 0;
    const int lt_label = labels[t];
    int la[ANCH];
#pragma unroll
    for (int k = 0; k < ANCH; k++) la[k] = labels[a0 + k];
    const unsigned ltm = (1u << lane) - 1u;

    // ---- Wait for K1's G / nrm ----
    asm volatile("griddepcontrol.wait;" ::: "memory");

    // Batched loads: one latency exposure for all three anchors.
    const float nt = nrm[t];
    float gv[ANCH], na[ANCH];
#pragma unroll
    for (int k = 0; k < ANCH; k++) gv[k] = G[(a0 + k) * N_PTS + t];
#pragma unroll
    for (int k = 0; k < ANCH; k++) na[k] = nrm[a0 + k];
    __syncthreads();   // cnts zeroed

    // ---- Compaction, all three anchors ----
#pragma unroll
    for (int k = 0; k < ANCH; k++) {
        const float dj = na[k] + nt - 2.f * gv[k];
        const bool same = (lt_label == la[k]);

        unsigned ms = __ballot_sync(0xFFFFFFFFu, same);
        unsigned md = ~ms;

        int bp = 0, bn = 0;
        if (lane == 0) {
            bp = atomicAdd(&cnts[k][0], __popc(ms));
            bn = atomicAdd(&cnts[k][1], __popc(md));
        }
        bp = __shfl_sync(0xFFFFFFFFu, bp, 0);
        bn = __shfl_sync(0xFFFFFFFFu, bn, 0);

        if (same) spos[k][bp + __popc(ms & ltm)] = dj;
        else      sneg[k][bn + __popc(md & ltm)] = dj;
    }
    __syncthreads();

    // ---- Pair loops ----
    float loss = 0.f, cnt = 0.f;
#pragma unroll
    for (int k = 0; k < ANCH; k++) {
        const int P = cnts[k][0];
        const int M = cnts[k][1];
        if (t < M) {
            const float dnm = sneg[k][t] - MARGIN;
            for (int p = 0; p < P; p++) {
                float L = spos[k][p] - dnm;
                if (L > 0.f && L < MARGIN) { loss += L; cnt += 1.f; }
            }
        }
    }

    // ---- Reduce + accumulate + last-block writeout ----
#pragma unroll
    for (int off = 16; off > 0; off >>= 1) {
        loss += __shfl_down_sync(0xFFFFFFFFu, loss, off);
        cnt  += __shfl_down_sync(0xFFFFFFFFu, cnt,  off);
    }
    if (lane == 0) { wl[warp] = loss; wc[warp] = cnt; }
    __syncthreads();

    if (t == 0) {
        float l = 0.f, c = 0.f;
#pragma unroll
        for (int w = 0; w < 12; w++) { l += wl[w]; c += wc[w]; }
        atomicAdd(&g_acc[0], l);
        atomicAdd(&g_acc[1], c);
        __threadfence();
        unsigned int done = atomicAdd(&g_ticket, 1u);
        if ((done % K2_GRID) == K2_GRID - 1) {
            __threadfence();
            out[0] = g_acc[0];
            out[1] = g_acc[1];
            for (int k = 2; k < out_size; k++) out[k] = 0.f;
            g_acc[0] = 0.f;
            g_acc[1] = 0.f;
        }
    }
}

extern "C" void kernel_launch(void* const* d_in, const int* in_sizes, int n_in,
                              void* d_out, int out_size) {
    const float* embeddings = (const float*)d_in[0];
    const int* labels = (const int*)d_in[1];
    float* out = (float*)d_out;

    float *G, *nrm;
    cudaGetSymbolAddress((void**)&G, g_gram);
    cudaGetSymbolAddress((void**)&nrm, g_nrm);

    dim3 grid1(12, 12);
    gram_kernel<<<grid1, 256>>>(embeddings, G, nrm);

    // Dependent launch with programmatic stream serialization (PDL):
    // K2's blocks may launch while K1 is still running; K2 waits on
    // griddepcontrol.wait before consuming G / nrm.
    cudaLaunchConfig_t cfg = {};
    cfg.gridDim = dim3(K2_GRID);
    cfg.blockDim = dim3(K2_BLK);
    cfg.dynamicSmemBytes = 0;
    cfg.stream = 0;
    cudaLaunchAttribute attr[1];
    attr[0].id = cudaLaunchAttributeProgrammaticStreamSerialization;
    attr[0].val.programmaticStreamSerializationAllowed = 1;
    cfg.attrs = attr;
    cfg.numAttrs = 1;
    cudaLaunchKernelEx(&cfg, triplet_kernel, (const float*)G, (const float*)nrm,
                       labels, out, out_size);
}